// round 13
// baseline (speedup 1.0000x reference)
#include <cuda_runtime.h>
#include <cstdint>

#define BATCH 65536
#define DIM   512
#define EPSF  1e-15f
#define MAXNF 0.996f   // 1 - 4e-3

// ---------------- scratch ----------------
// g_xfc / g_zt are stored K-PERMUTED within each 32-k tile:
//   element (row, k) lives at word row*512 + (k>>5)*32 + (k&3)*8 + ((k>>2)&7)
__device__ float g_xfc[(size_t)BATCH * DIM];
__device__ float g_zt [DIM * DIM];
__device__ float g_zn [DIM];
__device__ float g_ch [DIM];
__device__ float g_sh [DIM];
__device__ float g_fc2[BATCH];
__device__ float g_xc2[BATCH];

__device__ __forceinline__ unsigned f2tf(float f) {
    unsigned u; asm("cvt.rna.tf32.f32 %0, %1;" : "=r"(u) : "f"(f)); return u;
}
__device__ __forceinline__ uint32_t smem_u32(const void* p) {
    uint32_t a; asm("{ .reg .u64 t; cvta.to.shared.u64 t, %1; cvt.u32.u64 %0, t; }" : "=r"(a) : "l"(p));
    return a;
}
__device__ __forceinline__ void cpa16(uint32_t dst, const float* src) {
    asm volatile("cp.async.cg.shared.global [%0], [%1], 16;" :: "r"(dst), "l"(src));
}
#define CP_COMMIT() asm volatile("cp.async.commit_group;" ::: "memory")
#define CP_WAIT1()  asm volatile("cp.async.wait_group 1;" ::: "memory")
#define CP_WAIT0()  asm volatile("cp.async.wait_group 0;" ::: "memory")
#define CLUSTER_ARRIVE() asm volatile("barrier.cluster.arrive.aligned;" ::: "memory")
#define CLUSTER_WAIT()   asm volatile("barrier.cluster.wait.aligned;" ::: "memory")

__device__ __forceinline__ uint32_t cluster_rank() {
    uint32_t r; asm("mov.u32 %0, %%cluster_ctarank;" : "=r"(r));
    return r;
}
__device__ __forceinline__ float dsmem_ld(uint32_t local_addr, uint32_t peer) {
    uint32_t ra, v;
    asm volatile("mapa.shared::cluster.u32 %0, %1, %2;" : "=r"(ra) : "r"(local_addr), "r"(peer));
    asm volatile("ld.shared::cluster.b32 %0, [%1];" : "=r"(v) : "r"(ra));
    return __uint_as_float(v);
}

__device__ __forceinline__ void mma_tf32(float (&d)[4], const unsigned a0, const unsigned a1,
                                         const unsigned a2, const unsigned a3,
                                         const unsigned b0, const unsigned b1) {
    asm volatile("mma.sync.aligned.m16n8k8.row.col.f32.tf32.tf32.f32 "
                 "{%0,%1,%2,%3}, {%4,%5,%6,%7}, {%8,%9}, {%0,%1,%2,%3};\n"
                 : "+f"(d[0]), "+f"(d[1]), "+f"(d[2]), "+f"(d[3])
                 : "r"(a0), "r"(a1), "r"(a2), "r"(a3), "r"(b0), "r"(b1));
}

// ---------------- kernel 1: per-row prep (permuted g_xfc write) -------------
__global__ void k_prep(const float* __restrict__ xc, const float* __restrict__ xp,
                       float* __restrict__ out_xc)
{
    int row  = blockIdx.x * 8 + threadIdx.y;
    int lane = threadIdx.x;
    const float4* cv = (const float4*)(xc + (size_t)row * DIM);
    const float4* pv = (const float4*)(xp + (size_t)row * DIM);
    float4 c[4], p[4];
    float sxc = 0.f, sxp = 0.f, sxpc = 0.f;
#pragma unroll
    for (int i = 0; i < 4; i++) {
        c[i] = cv[lane + 32 * i];
        p[i] = pv[lane + 32 * i];
        sxc  += c[i].x*c[i].x + c[i].y*c[i].y + c[i].z*c[i].z + c[i].w*c[i].w;
        sxp  += p[i].x*p[i].x + p[i].y*p[i].y + p[i].z*p[i].z + p[i].w*p[i].w;
        sxpc += c[i].x*p[i].x + c[i].y*p[i].y + c[i].z*p[i].z + c[i].w*p[i].w;
    }
#pragma unroll
    for (int o = 16; o; o >>= 1) {
        sxc  += __shfl_xor_sync(0xffffffffu, sxc,  o);
        sxp  += __shfl_xor_sync(0xffffffffu, sxp,  o);
        sxpc += __shfl_xor_sync(0xffffffffu, sxpc, o);
    }
    float xy  = -sxpc;
    float den = fmaxf(1.f + 2.f*xy + sxp*sxc, EPSF);
    float ca  = -(1.f + 2.f*xy + sxc) / den;
    float cb  =  (1.f - sxp) / den;
    float sub2 = ca*ca*sxp + 2.f*ca*cb*sxpc + cb*cb*sxc;
    float sn   = sqrtf(fmaxf(sub2, EPSF));
    float at   = atanhf(fminf(sn, 1.f - 1e-7f));
    float Kbt  = fmaxf(1.f - sxp, EPSF) * at / sn;
    float un   = sqrtf(fmaxf(Kbt*Kbt*sub2, EPSF));
    float Kfc  = tanhf(un) / un * Kbt;
    float fc2  = Kfc*Kfc*sub2;
    float nc   = sqrtf(fmaxf(sxc, EPSF));
    float pc   = nc > MAXNF ? MAXNF / nc : 1.f;
    if (lane == 0) { g_fc2[row] = fc2; g_xc2[row] = sxc; }

    float4* xo = (float4*)(out_xc + (size_t)row * DIM);
#pragma unroll
    for (int i = 0; i < 4; i++) {
        int m = lane + 32 * i;               // float4 index: covers k = 4m..4m+3
        float* dst = g_xfc + (size_t)row * DIM + ((m >> 3) * 32) + (m & 7);
        dst[0]  = __uint_as_float(f2tf(Kfc * (ca * p[i].x + cb * c[i].x)));
        dst[8]  = __uint_as_float(f2tf(Kfc * (ca * p[i].y + cb * c[i].y)));
        dst[16] = __uint_as_float(f2tf(Kfc * (ca * p[i].z + cb * c[i].z)));
        dst[24] = __uint_as_float(f2tf(Kfc * (ca * p[i].w + cb * c[i].w)));
        float4 xq;
        xq.x = pc * c[i].x; xq.y = pc * c[i].y; xq.z = pc * c[i].z; xq.w = pc * c[i].w;
        xo[m] = xq;
    }
}

// ---------------- z preprocessing ------------------------------------------
__global__ void k_znorm(const float* __restrict__ z, const float* __restrict__ bias)
{
    int n = threadIdx.x;
    float acc = 0.f;
#pragma unroll 8
    for (int k = 0; k < DIM; k++) { float v = z[k * DIM + n]; acc += v * v; }
    g_zn[n] = sqrtf(fmaxf(acc, EPSF));
    float tb = 2.f * bias[n];
    g_ch[n] = coshf(tb);
    g_sh[n] = sinhf(tb);
}

__global__ void k_ztr(const float* __restrict__ z)
{
    __shared__ float t[32][33];
    int bx = blockIdx.x & 15, by = blockIdx.x >> 4;
    int tx = threadIdx.x, ty = threadIdx.y;
    int r0 = by * 32, c0 = bx * 32;
#pragma unroll
    for (int i = 0; i < 4; i++)
        t[ty + 8 * i][tx] = z[(size_t)(r0 + ty + 8 * i) * DIM + c0 + tx];
    __syncthreads();
#pragma unroll
    for (int i = 0; i < 4; i++) {
        int rr = ty + 8 * i;
        g_zt[(size_t)(c0 + rr) * DIM + by * 32 + (tx & 3) * 8 + (tx >> 2)]
            = __uint_as_float(f2tf(t[tx][rr]));
    }
}

// ---------------- cluster-fused GEMM + full epilogue -------------------------
// Cluster of 2 CTAs owns 128 rows x 512 cols; each CTA does 128x256.
// 512 threads, 16 warps (2m x 8n), warp tile 64x32. 3-stage cp.async,
// stage = A(128x32) 16KB + B(256x32) 32KB = 48KB.
static constexpr int STAGE_WORDS = 12288;        // 48KB
static constexpr int SMEM_BYTES  = 3 * 49152;    // 144KB

__global__ void __launch_bounds__(512, 1) __cluster_dims__(2, 1, 1)
k_gemm(const float* __restrict__ xcur, float* __restrict__ out,
       const float* __restrict__ alpha, const float* __restrict__ stepsz)
{
    extern __shared__ __align__(1024) float smem[];
    const uint32_t sb = smem_u32(smem);

    const uint32_t rank = cluster_rank();
    const int m0 = (blockIdx.x >> 1) * 128;
    const int n0 = (int)rank * 256;
    const int tid = threadIdx.x;
    const int wid = tid >> 5, lane = tid & 31;
    const int g = lane >> 2, t = lane & 3;
    const int wm = wid & 1, wn = wid >> 1;     // wn 0..7
    const int mb = wm * 64, nb = wn * 32;

    float acc[4][4][4];
#pragma unroll
    for (int mi = 0; mi < 4; mi++)
#pragma unroll
        for (int ni = 0; ni < 4; ni++)
#pragma unroll
            for (int ci = 0; ci < 4; ci++) acc[mi][ni][ci] = 0.f;

    auto load_tile = [&](int kt, int s) {
        const uint32_t st = sb + s * 49152;
        const float* Ab = g_xfc + (size_t)m0 * DIM + kt * 32;
        const float* Bb = g_zt  + (size_t)n0 * DIM + kt * 32;
#pragma unroll
        for (int i = 0; i < 2; i++) {
            int id = tid + 512 * i;
            int r = id >> 3, seg = id & 7;
            cpa16(st + (uint32_t)(r * 128 + (seg ^ (r & 7)) * 16),
                  Ab + (size_t)r * DIM + seg * 4);
        }
#pragma unroll
        for (int i = 0; i < 4; i++) {
            int id = tid + 512 * i;
            int r = id >> 3, seg = id & 7;     // r 0..255
            cpa16(st + 16384 + (uint32_t)(r * 128 + (seg ^ (r & 7)) * 16),
                  Bb + (size_t)r * DIM + seg * 4);
        }
        CP_COMMIT();
    };

    load_tile(0, 0);
    load_tile(1, 1);

    for (int kt = 0; kt < 16; kt++) {
        if (kt == 15) { CP_WAIT0(); } else { CP_WAIT1(); }
        __syncthreads();
        if (kt + 2 < 16) load_tile(kt + 2, (kt + 2) % 3);

        const float4* As4 = (const float4*)(smem + (kt % 3) * STAGE_WORDS);
        const float4* Bs4 = As4 + 1024;        // +16KB
#pragma unroll
        for (int b = 0; b < 2; b++) {
            const int ch = (2 * t + b) ^ g;
            float4 vb[4];
#pragma unroll
            for (int ni = 0; ni < 4; ni++)
                vb[ni] = Bs4[(nb + 8 * ni + g) * 8 + ch];
#pragma unroll
            for (int mi = 0; mi < 4; mi++) {
                int r = mb + 16 * mi + g;
                float4 va0 = As4[ r      * 8 + ch];
                float4 va1 = As4[(r + 8) * 8 + ch];
#pragma unroll
                for (int ni = 0; ni < 4; ni++)
                    mma_tf32(acc[mi][ni],
                             __float_as_uint(va0.x), __float_as_uint(va1.x),
                             __float_as_uint(va0.y), __float_as_uint(va1.y),
                             __float_as_uint(vb[ni].x), __float_as_uint(vb[ni].y));
#pragma unroll
                for (int ni = 0; ni < 4; ni++)
                    mma_tf32(acc[mi][ni],
                             __float_as_uint(va0.z), __float_as_uint(va1.z),
                             __float_as_uint(va0.w), __float_as_uint(va1.w),
                             __float_as_uint(vb[ni].z), __float_as_uint(vb[ni].w));
            }
        }
    }
    __syncthreads();   // stage smem free; reuse for reductions

    float* red_s2 = smem;            // [8][128]
    float* red_dx = smem + 1024;     // [8][128]
    float* s2h    = smem + 2048;     // [128] per-CTA half sums
    float* dxh    = smem + 2176;
    float* f1_s   = smem + 2304;     // [128]
    float* f2_s   = smem + 2432;

    // ---- transform acc -> w in place; accumulate per-row s2 / dxw ----
    float ps2[4][2], pdx[4][2];
#pragma unroll
    for (int mi = 0; mi < 4; mi++) { ps2[mi][0]=ps2[mi][1]=0.f; pdx[mi][0]=pdx[mi][1]=0.f; }

#pragma unroll
    for (int mi = 0; mi < 4; mi++) {
        int r0 = m0 + mb + 16 * mi + g;
        float f0 = g_fc2[r0], f1v = g_fc2[r0 + 8];
        float pa0 = 1.f + f0,  pa1 = 1.f + f1v;
        float id0 = 1.f / fmaxf(1.f - f0,  EPSF);
        float id1 = 1.f / fmaxf(1.f - f1v, EPSF);
#pragma unroll
        for (int ni = 0; ni < 4; ni++) {
            int c = n0 + nb + 8 * ni + 2 * t;
            float zn0 = g_zn[c], zn1 = g_zn[c + 1];
            float iz0 = 1.f / zn0, iz1 = 1.f / zn1;
            float ch0 = g_ch[c], ch1 = g_ch[c + 1];
            float sh0 = g_sh[c], sh1 = g_sh[c + 1];
            float in00 = acc[mi][ni][0] * iz0, in01 = acc[mi][ni][1] * iz1;
            float in10 = acc[mi][ni][2] * iz0, in11 = acc[mi][ni][3] * iz1;
            float w00 = sinhf(2.f * zn0 * asinhf((2.f * in00 * ch0 - pa0 * sh0) * id0));
            float w01 = sinhf(2.f * zn1 * asinhf((2.f * in01 * ch1 - pa0 * sh1) * id0));
            float w10 = sinhf(2.f * zn0 * asinhf((2.f * in10 * ch0 - pa1 * sh0) * id1));
            float w11 = sinhf(2.f * zn1 * asinhf((2.f * in11 * ch1 - pa1 * sh1) * id1));
            acc[mi][ni][0] = w00; acc[mi][ni][1] = w01;
            acc[mi][ni][2] = w10; acc[mi][ni][3] = w11;
            float2 x0 = *(const float2*)&xcur[(size_t)r0 * DIM + c];
            float2 x1 = *(const float2*)&xcur[(size_t)(r0 + 8) * DIM + c];
            ps2[mi][0] += w00 * w00 + w01 * w01;
            ps2[mi][1] += w10 * w10 + w11 * w11;
            pdx[mi][0] += w00 * x0.x + w01 * x0.y;
            pdx[mi][1] += w10 * x1.x + w11 * x1.y;
        }
    }
#pragma unroll
    for (int mi = 0; mi < 4; mi++)
#pragma unroll
        for (int h = 0; h < 2; h++) {
            ps2[mi][h] += __shfl_xor_sync(0xffffffffu, ps2[mi][h], 1);
            ps2[mi][h] += __shfl_xor_sync(0xffffffffu, ps2[mi][h], 2);
            pdx[mi][h] += __shfl_xor_sync(0xffffffffu, pdx[mi][h], 1);
            pdx[mi][h] += __shfl_xor_sync(0xffffffffu, pdx[mi][h], 2);
        }
    if (t == 0) {
#pragma unroll
        for (int mi = 0; mi < 4; mi++)
#pragma unroll
            for (int h = 0; h < 2; h++) {
                int rl = mb + 16 * mi + 8 * h + g;
                red_s2[wn * 128 + rl] = ps2[mi][h];
                red_dx[wn * 128 + rl] = pdx[mi][h];
            }
    }
    __syncthreads();
    if (tid < 128) {
        float s2 = 0.f, dx = 0.f;
#pragma unroll
        for (int j = 0; j < 8; j++) { s2 += red_s2[j * 128 + tid]; dx += red_dx[j * 128 + tid]; }
        s2h[tid] = s2;
        dxh[tid] = dx;
    }
    // make partials visible cluster-wide, then read the partner's
    CLUSTER_ARRIVE();
    CLUSTER_WAIT();

    if (tid < 128) {
        const uint32_t peer = rank ^ 1u;
        float s2  = s2h[tid] + dsmem_ld(sb + (2048 + tid) * 4, peer);
        float dxw = dxh[tid] + dsmem_ld(sb + (2176 + tid) * 4, peer);
        float xc2  = g_xc2[m0 + tid];
        float step = 1.f / (1.f + expf(-stepsz[0]));
        float av   = 1.f / (1.f + expf(-alpha[0]));

        float q  = sqrtf(1.f + s2);
        float yn = sqrtf(fmaxf(s2 / ((1.f + q) * (1.f + q)), EPSF));
        float kv = atanhf(fminf(yn, 1.f - 1e-7f)) / (yn * (1.f + q));
        float un   = sqrtf(fmaxf(step * step * kv * kv * s2, EPSF));
        float lamf = fmaxf(1.f - xc2, EPSF);
        float th   = tanhf(un / lamf);
        float ky   = th * step * kv / un;
        float y2   = ky * ky * s2;
        float xy   = ky * dxw;
        float den  = fmaxf(1.f + 2.f * xy + xc2 * y2, EPSF);
        float c1   = (1.f + 2.f * xy + y2) / den;
        float c2   = (1.f - xc2) * ky / den;
        float nu2 = c1 * c1 * xc2 + 2.f * c1 * c2 * dxw + c2 * c2 * s2;
        float nu  = sqrtf(fmaxf(nu2, EPSF));
        float pu  = nu > MAXNF ? MAXNF / nu : 1.f;
        float b1 = pu * c1, b2 = pu * c2, nuf = pu * nu;
        float nc  = sqrtf(fmaxf(xc2, EPSF));
        float pc  = nc > MAXNF ? MAXNF / nc : 1.f;
        float ncf = pc * nc;
        float t1 = tanhf(av * atanhf(fminf(ncf, 1.f - 1e-7f)));
        float q1 = t1 * pc / ncf;
        float t2 = tanhf((1.f - av) * atanhf(fminf(nuf, 1.f - 1e-7f)));
        float q2 = t2 / nuf;
        float r1 = q2 * b1, r2 = q2 * b2;
        float X2 = t1 * t1, Y2 = t2 * t2;
        float XY = q1 * (r1 * xc2 + r2 * dxw);
        float dn = fmaxf(1.f + 2.f * XY + X2 * Y2, EPSF);
        float h1 = ((1.f + 2.f * XY + Y2) * q1 + (1.f - X2) * r1) / dn;
        float h2 = (1.f - X2) * r2 / dn;
        float nn = sqrtf(fmaxf(h1 * h1 * xc2 + 2.f * h1 * h2 * dxw + h2 * h2 * s2, EPSF));
        float pn = nn > MAXNF ? MAXNF / nn : 1.f;
        f1_s[tid] = pn * h1;
        f2_s[tid] = pn * h2;
    }
    __syncthreads();        // all DSMEM reads within this CTA are done
    CLUSTER_ARRIVE();       // signal partner: safe to exit after wait

    // ---- final rank-1 write from registers ----
#pragma unroll
    for (int mi = 0; mi < 4; mi++) {
        int rl0 = mb + 16 * mi + g;
        int r0 = m0 + rl0;
        float f10 = f1_s[rl0],     f20 = f2_s[rl0];
        float f11 = f1_s[rl0 + 8], f21 = f2_s[rl0 + 8];
#pragma unroll
        for (int ni = 0; ni < 4; ni++) {
            int c = n0 + nb + 8 * ni + 2 * t;
            float2 x0 = *(const float2*)&xcur[(size_t)r0 * DIM + c];
            float2 x1 = *(const float2*)&xcur[(size_t)(r0 + 8) * DIM + c];
            float2 o0, o1;
            o0.x = f10 * x0.x + f20 * acc[mi][ni][0];
            o0.y = f10 * x0.y + f20 * acc[mi][ni][1];
            o1.x = f11 * x1.x + f21 * acc[mi][ni][2];
            o1.y = f11 * x1.y + f21 * acc[mi][ni][3];
            *(float2*)&out[(size_t)r0 * DIM + c]       = o0;
            *(float2*)&out[(size_t)(r0 + 8) * DIM + c] = o1;
        }
    }
    CLUSTER_WAIT();         // don't free smem while partner may still read
}

// ---------------- launch -----------------------------------------------------
extern "C" void kernel_launch(void* const* d_in, const int* in_sizes, int n_in,
                              void* d_out, int out_size)
{
    const float* xcur   = (const float*)d_in[0];
    const float* xprev  = (const float*)d_in[1];
    const float* z      = (const float*)d_in[2];
    const float* bias   = (const float*)d_in[3];
    const float* alpha  = (const float*)d_in[4];
    const float* stepsz = (const float*)d_in[5];
    float* out = (float*)d_out;

    cudaFuncSetAttribute(k_gemm, cudaFuncAttributeMaxDynamicSharedMemorySize, SMEM_BYTES);

    k_prep<<<BATCH / 8, dim3(32, 8)>>>(xcur, xprev, out + (size_t)BATCH * DIM);
    k_znorm<<<1, DIM>>>(z, bias);
    k_ztr<<<256, dim3(32, 8)>>>(z);
    k_gemm<<<BATCH / 64, 512, SMEM_BYTES>>>(xcur, out, alpha, stepsz);
}